// round 10
// baseline (speedup 1.0000x reference)
#include <cuda_runtime.h>
#include <cuda_fp16.h>
#include <cstdint>
#include <math.h>

#define N_INST 256
#define BATCH  128
#define IN_DIM 1024
#define L_DIM  512

// ---------------- device scratch (allocation-free rule) ----------------
__device__ __align__(256) __half g_v[L_DIM * IN_DIM];  // [l][k] transposed, fp16
__device__ __align__(256) __half g_u[L_DIM * IN_DIM];
__device__ float g_part[1024 * BATCH];   // partial scores per (instance, l-chunk)

// ---------------- helpers ----------------
__device__ __forceinline__ uint32_t smem_u32(const void* p) {
    uint32_t a;
    asm("{ .reg .u64 t; cvta.to.shared.u64 t, %1; cvt.u32.u64 %0, t; }" : "=r"(a) : "l"(p));
    return a;
}
// 128B-row swizzle (SW128): XOR row bits [9:7] into 16B-chunk bits [6:4]
#define SWZ128(off) ((off) ^ (((off) >> 3) & 0x70))

#define CP16(dst, src) \
    asm volatile("cp.async.cg.shared.global [%0], [%1], 16;" :: "r"(dst), "l"(src))
#define CP_COMMIT() asm volatile("cp.async.commit_group;" ::: "memory")
#define CP_WAIT(n)  asm volatile("cp.async.wait_group %0;" :: "n"(n) : "memory")

__device__ __forceinline__ void ldsm4(uint32_t* r, uint32_t addr) {
    asm volatile("ldmatrix.sync.aligned.m8n8.x4.shared.b16 {%0,%1,%2,%3}, [%4];"
                 : "=r"(r[0]), "=r"(r[1]), "=r"(r[2]), "=r"(r[3]) : "r"(addr));
}
__device__ __forceinline__ void mma16816(float* c, const uint32_t* a, const uint32_t* b) {
    asm volatile("mma.sync.aligned.m16n8k16.row.col.f32.f16.f16.f32 "
                 "{%0,%1,%2,%3}, {%4,%5,%6,%7}, {%8,%9}, {%0,%1,%2,%3};"
                 : "+f"(c[0]), "+f"(c[1]), "+f"(c[2]), "+f"(c[3])
                 : "r"(a[0]), "r"(a[1]), "r"(a[2]), "r"(a[3]), "r"(b[0]), "r"(b[1]));
}
__device__ __forceinline__ uint32_t f2h2(float a, float b) {
    __half2 h = __floats2half2_rn(a, b);
    return *(uint32_t*)&h;
}
__device__ __forceinline__ float fast_tanh(float x) {
    float t = __expf(2.0f * x);
    return (t - 1.0f) / (t + 1.0f);
}
__device__ __forceinline__ float fast_sigmoid(float x) {
    return 1.0f / (1.0f + __expf(-x));
}

// ---------------- prep kernel (V/U transpose+convert only; X is fused) ------
__global__ void prep_vu_kernel(const float* __restrict__ v, const float* __restrict__ u) {
    int gid = blockIdx.x * 256 + threadIdx.x;               // 524288 threads
    int k = gid & (IN_DIM - 1);
    int l = gid >> 10;
    size_t o = (size_t)l * IN_DIM + k;
    g_v[o] = __float2half_rn(v[(size_t)k * L_DIM + l]);
    g_u[o] = __float2half_rn(u[(size_t)k * L_DIM + l]);
}

// ---------------- main fused GEMM kernel ----------------
// One CTA per (instance n, l-chunk lc). 512 threads / 16 warps.
// Warp tile 32 M x 64 N: mw = wid&3 (rows), nw = wid>>2 (cols; <2: V, >=2: U).
// BK=64: 4 k-steps per pipeline stage, 16 iterations.
// A tile is loaded from fp32 X via LDG + in-register convert + STS (fused prep).
// SMEM map (bytes):
#define SM_W      0          // 128 f32 = 512
#define SM_RED    512        // 256 f32 = 1024
#define SM_STASH  1536       // 128 rows x 264B (fp16, padded) -> ends 35328
#define STASH_STRIDE 264
#define SM_TILES  35328      // 3 stages x 48KB
#define BUF_STRIDE 49152     // per stage: A 16K (128 rows x 128B), B 32K (256 rows x 128B)
#define OFF_A     0
#define OFF_B     16384
#define SM_TOTAL  (SM_TILES + 3 * BUF_STRIDE)   // 182784

#define BK 64
#define NI (IN_DIM / BK)     // 16 K-iterations

__global__ void __launch_bounds__(512, 1)
mil_gemm_kernel(const float* __restrict__ x, const float* __restrict__ w)
{
    extern __shared__ char smem[];
    const int task = blockIdx.x;       // 0..1023
    const int n    = task >> 2;
    const int lc   = task & 3;
    const int l0   = lc * 128;
    const int tid  = threadIdx.x;
    const int lane = tid & 31;
    const int wid  = tid >> 5;
    const int mw   = wid & 3;    // M band: rows mw*32..+31
    const int nw   = wid >> 2;   // N band: combined cols nw*64..+63 (nw<2: V, nw>=2: U)
    const uint32_t smem_base = smem_u32(smem);

    // w slice for this l-chunk into smem
    float* ws = (float*)(smem + SM_W);
    if (tid < 128) ws[tid] = w[l0 + tid];

    const size_t lofs = (size_t)l0 * IN_DIM;

    // ---- A (X) fused-convert load assignment ----
    // Thread covers row = tid>>2, k-chunk seg of 16 fp32 (=32B fp16 in smem).
    const int arow = tid >> 2;          // 0..127
    const int aseg = tid & 3;           // 0..3 (16 k each)
    const float4* axrow = (const float4*)(x + ((size_t)n * BATCH + arow) * IN_DIM) + aseg * 4;
    const uint32_t dstA0 = SM_TILES + OFF_A + SWZ128(arow * 128 + aseg * 32);
    const uint32_t dstA1 = SM_TILES + OFF_A + SWZ128(arow * 128 + aseg * 32 + 16);

    // Loads 16 fp32 of row `arow`, k-range [k0+aseg*16, +16), converts, stores to stage buf.
    auto load_convert_A = [&](int k0, uint32_t bb) {
        const float4* s = axrow + (k0 >> 2);
        float4 f0 = s[0], f1 = s[1], f2 = s[2], f3 = s[3];
        uint4 q0, q1;
        q0.x = f2h2(f0.x, f0.y); q0.y = f2h2(f0.z, f0.w);
        q0.z = f2h2(f1.x, f1.y); q0.w = f2h2(f1.z, f1.w);
        q1.x = f2h2(f2.x, f2.y); q1.y = f2h2(f2.z, f2.w);
        q1.z = f2h2(f3.x, f3.y); q1.w = f2h2(f3.z, f3.w);
        *(uint4*)(smem + (bb - smem_base) + dstA0) = q0;
        *(uint4*)(smem + (bb - smem_base) + dstA1) = q1;
    };

    // ---- B cp.async assignments (per stage: 2048 16B chunks; thread gets 4) ----
    const __half* srcB[4];
    uint32_t dstB[4];
#pragma unroll
    for (int j = 0; j < 4; j++) {
        int idx  = j * 512 + tid;
        int brow = idx >> 3;
        int seg  = idx & 7;
        const __half* mat = (brow < 128) ? g_v : g_u;
        srcB[j] = mat + lofs + (size_t)(brow & 127) * IN_DIM + seg * 8;
        dstB[j] = SM_TILES + OFF_B + SWZ128(brow * 128 + seg * 16);
    }

    float acc[2][8][4];
#pragma unroll
    for (int mt = 0; mt < 2; mt++)
#pragma unroll
        for (int nt = 0; nt < 8; nt++)
#pragma unroll
            for (int r = 0; r < 4; r++) acc[mt][nt][r] = 0.f;

    // ---- prologue: B stages 0,1 via cp.async; A stages 0,1 via LDG+STS ----
#pragma unroll
    for (int s = 0; s < 2; s++) {
        uint32_t bb = smem_base + s * BUF_STRIDE;
        int k0 = s * BK;
#pragma unroll
        for (int j = 0; j < 4; j++) CP16(bb + dstB[j], srcB[j] + k0);
        CP_COMMIT();
    }
    load_convert_A(0, smem_base);
    load_convert_A(BK, smem_base + BUF_STRIDE);

    int slot = 0, nslot = 2;
    for (int it = 0; it < NI; it++) {
        if (it + 1 < NI) { CP_WAIT(1); } else { CP_WAIT(0); }
        __syncthreads();
        if (it + 2 < NI) {
            uint32_t bb = smem_base + nslot * BUF_STRIDE;
            int k0 = (it + 2) * BK;
#pragma unroll
            for (int j = 0; j < 4; j++) CP16(bb + dstB[j], srcB[j] + k0);
            CP_COMMIT();
            load_convert_A(k0, bb);      // visible after sync at top of it+1 (< it+2)
            nslot = (nslot == 2) ? 0 : nslot + 1;
        }

        const uint32_t bb = smem_base + slot * BUF_STRIDE;
        slot = (slot == 2) ? 0 : slot + 1;
        const uint32_t aA = bb + SM_TILES + OFF_A;
        const uint32_t bB = bb + SM_TILES + OFF_B;

#pragma unroll
        for (int ks = 0; ks < 4; ks++) {
            // A fragments: row = mw*32 + mt*16 + (lane&15), k-half = (lane>>4)*8
            uint32_t af[2][4];
            const uint32_t akoff = ks * 32 + (lane >> 4) * 16;
#pragma unroll
            for (int mt = 0; mt < 2; mt++) {
                uint32_t rowb = (mw * 32 + mt * 16 + (lane & 15)) * 128;
                ldsm4(af[mt], aA + SWZ128(rowb + akoff));
            }
            const uint32_t bkoff = ks * 32 + ((lane >> 3) & 1) * 16;
#pragma unroll
            for (int ntp = 0; ntp < 4; ntp++) {
                uint32_t rowb = (nw * 64 + ntp * 16 + ((lane >> 4) & 1) * 8 + (lane & 7)) * 128;
                uint32_t bf[4];
                ldsm4(bf, bB + SWZ128(rowb + bkoff));
#pragma unroll
                for (int half = 0; half < 2; half++) {
                    int nt = ntp * 2 + half;
#pragma unroll
                    for (int mt = 0; mt < 2; mt++)
                        mma16816(acc[mt][nt], af[mt], bf + half * 2);
                }
            }
        }
    }
    __syncthreads();

    // ---- epilogue ----
    if (nw < 2) {
        // V warps: stash tanh as fp16
#pragma unroll
        for (int mt = 0; mt < 2; mt++)
#pragma unroll
            for (int nt = 0; nt < 8; nt++) {
                int col = nw * 64 + nt * 8 + (lane & 3) * 2;
#pragma unroll
                for (int half = 0; half < 2; half++) {
                    int row = mw * 32 + mt * 16 + half * 8 + (lane >> 2);
                    float h0 = fast_tanh(acc[mt][nt][half * 2 + 0]);
                    float h1 = fast_tanh(acc[mt][nt][half * 2 + 1]);
                    *(__half2*)(smem + SM_STASH + row * STASH_STRIDE + col * 2) =
                        __floats2half2_rn(h0, h1);
                }
            }
    }
    __syncthreads();

    float rowacc[4] = {0.f, 0.f, 0.f, 0.f};
    if (nw >= 2) {
        // U warps: gate + weight
#pragma unroll
        for (int mt = 0; mt < 2; mt++)
#pragma unroll
            for (int nt = 0; nt < 8; nt++) {
                int vcol = (nw - 2) * 64 + nt * 8 + (lane & 3) * 2;
                float w0 = ws[vcol + 0];
                float w1 = ws[vcol + 1];
#pragma unroll
                for (int half = 0; half < 2; half++) {
                    int row = mw * 32 + mt * 16 + half * 8 + (lane >> 2);
                    __half2 hh = *(const __half2*)(smem + SM_STASH +
                                                   row * STASH_STRIDE + vcol * 2);
                    float g0 = fast_sigmoid(acc[mt][nt][half * 2 + 0]);
                    float g1 = fast_sigmoid(acc[mt][nt][half * 2 + 1]);
                    rowacc[mt * 2 + half] += __low2float(hh)  * g0 * w0 +
                                             __high2float(hh) * g1 * w1;
                }
            }
    }
    __syncthreads();

    // ---- final reduction: 8 U warps -> 128 partial scores ----
    float* red = (float*)(smem + SM_RED);
    if (nw >= 2) {
#pragma unroll
        for (int ri = 0; ri < 4; ri++) {
            float p = rowacc[ri];
            p += __shfl_xor_sync(0xffffffffu, p, 1);
            p += __shfl_xor_sync(0xffffffffu, p, 2);
            if ((lane & 3) == 0) {
                int row = mw * 32 + (ri >> 1) * 16 + (ri & 1) * 8 + (lane >> 2);
                red[(nw - 2) * 128 + row] = p;
            }
        }
    }
    __syncthreads();
    if (tid < BATCH)
        g_part[(size_t)task * BATCH + tid] = red[tid] + red[128 + tid];
}

// ---------------- softmax over instance axis (sums 4 l-chunk partials) ----------------
__global__ void softmax_kernel(float* __restrict__ out)
{
    const int b   = blockIdx.x;    // 0..127
    const int tid = threadIdx.x;   // 0..255 == n
    __shared__ float sh[256];

    const float* p = g_part + ((size_t)tid * 4) * BATCH + b;
    float s = p[0] + p[BATCH] + p[2 * BATCH] + p[3 * BATCH];
    sh[tid] = s;
    __syncthreads();
#pragma unroll
    for (int off = 128; off > 0; off >>= 1) {
        if (tid < off) sh[tid] = fmaxf(sh[tid], sh[tid + off]);
        __syncthreads();
    }
    float m = sh[0];
    __syncthreads();
    float e = __expf(s - m);
    sh[tid] = e;
    __syncthreads();
#pragma unroll
    for (int off = 128; off > 0; off >>= 1) {
        if (tid < off) sh[tid] += sh[tid + off];
        __syncthreads();
    }
    out[(size_t)tid * BATCH + b] = e / sh[0];
}

extern "C" void kernel_launch(void* const* d_in, const int* in_sizes, int n_in,
                              void* d_out, int out_size)
{
    const float* x = (const float*)d_in[0];
    const float* v = (const float*)d_in[1];
    const float* u = (const float*)d_in[2];
    const float* w = (const float*)d_in[3];
    float* out = (float*)d_out;

    cudaFuncSetAttribute(mil_gemm_kernel,
                         cudaFuncAttributeMaxDynamicSharedMemorySize, SM_TOTAL);

    prep_vu_kernel<<<2048, 256>>>(v, u);
    mil_gemm_kernel<<<1024, 512, SM_TOTAL>>>(x, w);
    softmax_kernel<<<BATCH, 256>>>(out);
}

// round 11
// speedup vs baseline: 1.3880x; 1.3880x over previous
#include <cuda_runtime.h>
#include <cuda_fp16.h>
#include <cstdint>
#include <math.h>

#define N_INST 256
#define BATCH  128
#define IN_DIM 1024
#define L_DIM  512

// ---------------- device scratch (allocation-free rule) ----------------
__device__ __align__(256) __half g_x[(size_t)N_INST * BATCH * IN_DIM]; // 64MB fp16
__device__ __align__(256) __half g_v[L_DIM * IN_DIM];  // [l][k] transposed, fp16
__device__ __align__(256) __half g_u[L_DIM * IN_DIM];
__device__ float g_part[2048 * BATCH];   // partial scores per (instance, 64-col l-chunk)

// ---------------- helpers ----------------
__device__ __forceinline__ uint32_t smem_u32(const void* p) {
    uint32_t a;
    asm("{ .reg .u64 t; cvta.to.shared.u64 t, %1; cvt.u32.u64 %0, t; }" : "=r"(a) : "l"(p));
    return a;
}
// 128B-row swizzle (SW128): XOR row bits [9:7] into 16B-chunk bits [6:4]
#define SWZ128(off) ((off) ^ (((off) >> 3) & 0x70))

#define CP16(dst, src) \
    asm volatile("cp.async.cg.shared.global [%0], [%1], 16;" :: "r"(dst), "l"(src))
#define CP_COMMIT() asm volatile("cp.async.commit_group;" ::: "memory")
#define CP_WAIT(n)  asm volatile("cp.async.wait_group %0;" :: "n"(n) : "memory")

__device__ __forceinline__ void ldsm4(uint32_t* r, uint32_t addr) {
    asm volatile("ldmatrix.sync.aligned.m8n8.x4.shared.b16 {%0,%1,%2,%3}, [%4];"
                 : "=r"(r[0]), "=r"(r[1]), "=r"(r[2]), "=r"(r[3]) : "r"(addr));
}
__device__ __forceinline__ void mma16816(float* c, const uint32_t* a, const uint32_t* b) {
    asm volatile("mma.sync.aligned.m16n8k16.row.col.f32.f16.f16.f32 "
                 "{%0,%1,%2,%3}, {%4,%5,%6,%7}, {%8,%9}, {%0,%1,%2,%3};"
                 : "+f"(c[0]), "+f"(c[1]), "+f"(c[2]), "+f"(c[3])
                 : "r"(a[0]), "r"(a[1]), "r"(a[2]), "r"(a[3]), "r"(b[0]), "r"(b[1]));
}
__device__ __forceinline__ float fast_tanh(float x) {
    float t = __expf(2.0f * x);
    return (t - 1.0f) / (t + 1.0f);
}
__device__ __forceinline__ float fast_sigmoid(float x) {
    return 1.0f / (1.0f + __expf(-x));
}

// ---------------- prep kernels ----------------
__global__ void prep_x_kernel(const float4* __restrict__ x4) {
    size_t i = (size_t)blockIdx.x * 256 + threadIdx.x;      // 8388608 threads
    float4 f = x4[i];
    __half2 h01 = __floats2half2_rn(f.x, f.y);
    __half2 h23 = __floats2half2_rn(f.z, f.w);
    size_t o = i * 4;
    __half2* dst = (__half2*)(g_x + o);
    dst[0] = h01;
    dst[1] = h23;
}

__global__ void prep_vu_kernel(const float* __restrict__ v, const float* __restrict__ u) {
    int gid = blockIdx.x * 256 + threadIdx.x;               // 524288 threads
    int k = gid & (IN_DIM - 1);
    int l = gid >> 10;
    size_t o = (size_t)l * IN_DIM + k;
    g_v[o] = __float2half_rn(v[(size_t)k * L_DIM + l]);
    g_u[o] = __float2half_rn(u[(size_t)k * L_DIM + l]);
}

// ---------------- main fused GEMM kernel ----------------
// One CTA per (instance n, 64-col l-chunk). 256 threads / 8 warps, 2 CTAs/SM.
// Combined B tile: 128 rows = 64 V-rows then 64 U-rows, BK=64 columns.
// Warp tile 32 M x 64 N: mw = wid&3 (row band), nw = wid>>2 (0: V, 1: U).
// SMEM map (bytes):
#define SM_W      0          // 64 f32 = 256
#define SM_TILES  1024       // 3 stages x 32KB
#define BUF_STRIDE 32768     // per stage: A 16K (128 rows x 128B), B 16K (128 rows x 128B)
#define OFF_A     0
#define OFF_B     16384
#define SM_STASH  SM_TILES   // stash ALIASES stage buffers (used only after mainloop)
#define STASH_STRIDE 136     // 64 cols fp16 + 8B pad
#define SM_TOTAL  (SM_TILES + 3 * BUF_STRIDE)   // 99328

#define BK 64
#define NI (IN_DIM / BK)     // 16 K-iterations

__global__ void __launch_bounds__(256, 2)
mil_gemm_kernel(const float* __restrict__ w)
{
    extern __shared__ char smem[];
    const int task = blockIdx.x;       // 0..2047
    const int n    = task >> 3;
    const int l0   = (task & 7) * 64;
    const int tid  = threadIdx.x;
    const int lane = tid & 31;
    const int wid  = tid >> 5;
    const int mw   = wid & 3;    // M band: rows mw*32..+31
    const int nw   = wid >> 2;   // 0: V cols (B rows 0-63), 1: U cols (B rows 64-127)
    const uint32_t smem_base = smem_u32(smem);

    // w slice for this l-chunk into smem
    float* ws = (float*)(smem + SM_W);
    if (tid < 64) ws[tid] = w[l0 + tid];

    const __half* xp = g_x + (size_t)n * BATCH * IN_DIM;

    // ---- per-thread cp.async assignments (per stage: A 1024 + B 1024 chunks, 8/thread) ----
    const __half* srcA[4];
    uint32_t dstA[4];
#pragma unroll
    for (int j = 0; j < 4; j++) {
        int idx = j * 256 + tid;
        int row = idx >> 3;
        int seg = idx & 7;
        srcA[j] = xp + (size_t)row * IN_DIM + seg * 8;
        dstA[j] = SM_TILES + OFF_A + SWZ128(row * 128 + seg * 16);
    }
    const __half* srcB[4];
    uint32_t dstB[4];
#pragma unroll
    for (int j = 0; j < 4; j++) {
        int idx  = j * 256 + tid;
        int brow = idx >> 3;          // 0..127: 0-63 V, 64-127 U
        int seg  = idx & 7;
        const __half* mat = (brow < 64) ? g_v : g_u;
        srcB[j] = mat + (size_t)(l0 + (brow & 63)) * IN_DIM + seg * 8;
        dstB[j] = SM_TILES + OFF_B + SWZ128(brow * 128 + seg * 16);
    }

    float acc[2][8][4];
#pragma unroll
    for (int mt = 0; mt < 2; mt++)
#pragma unroll
        for (int nt = 0; nt < 8; nt++)
#pragma unroll
            for (int r = 0; r < 4; r++) acc[mt][nt][r] = 0.f;

    // ---- prologue: stages 0 and 1 ----
#pragma unroll
    for (int s = 0; s < 2; s++) {
        uint32_t bb = smem_base + s * BUF_STRIDE;
        int k0 = s * BK;
#pragma unroll
        for (int j = 0; j < 4; j++) CP16(bb + dstA[j], srcA[j] + k0);
#pragma unroll
        for (int j = 0; j < 4; j++) CP16(bb + dstB[j], srcB[j] + k0);
        CP_COMMIT();
    }

    int slot = 0, nslot = 2;
    for (int it = 0; it < NI; it++) {
        if (it + 1 < NI) { CP_WAIT(1); } else { CP_WAIT(0); }
        __syncthreads();
        if (it + 2 < NI) {
            uint32_t bb = smem_base + nslot * BUF_STRIDE;
            int k0 = (it + 2) * BK;
#pragma unroll
            for (int j = 0; j < 4; j++) CP16(bb + dstA[j], srcA[j] + k0);
#pragma unroll
            for (int j = 0; j < 4; j++) CP16(bb + dstB[j], srcB[j] + k0);
            CP_COMMIT();
            nslot = (nslot == 2) ? 0 : nslot + 1;
        }

        const uint32_t bb = smem_base + slot * BUF_STRIDE;
        slot = (slot == 2) ? 0 : slot + 1;
        const uint32_t aA = bb + SM_TILES + OFF_A;
        const uint32_t bB = bb + SM_TILES + OFF_B;

#pragma unroll
        for (int ks = 0; ks < 4; ks++) {
            // A fragments: row = mw*32 + mt*16 + (lane&15), k-half = (lane>>4)*8
            uint32_t af[2][4];
            const uint32_t akoff = ks * 32 + (lane >> 4) * 16;
#pragma unroll
            for (int mt = 0; mt < 2; mt++) {
                uint32_t rowb = (mw * 32 + mt * 16 + (lane & 15)) * 128;
                ldsm4(af[mt], aA + SWZ128(rowb + akoff));
            }
            const uint32_t bkoff = ks * 32 + ((lane >> 3) & 1) * 16;
#pragma unroll
            for (int ntp = 0; ntp < 4; ntp++) {
                uint32_t rowb = (nw * 64 + ntp * 16 + ((lane >> 4) & 1) * 8 + (lane & 7)) * 128;
                uint32_t bf[4];
                ldsm4(bf, bB + SWZ128(rowb + bkoff));
#pragma unroll
                for (int half = 0; half < 2; half++) {
                    int nt = ntp * 2 + half;
#pragma unroll
                    for (int mt = 0; mt < 2; mt++)
                        mma16816(acc[mt][nt], af[mt], bf + half * 2);
                }
            }
        }
    }
    __syncthreads();   // mainloop smem reads done; stage buffers may now be reused as stash

    // ---- epilogue ----
    if (nw == 0) {
        // V warps: stash tanh as fp16 (rows mw*32..+31, all 64 chunk cols)
#pragma unroll
        for (int mt = 0; mt < 2; mt++)
#pragma unroll
            for (int nt = 0; nt < 8; nt++) {
                int col = nt * 8 + (lane & 3) * 2;
#pragma unroll
                for (int half = 0; half < 2; half++) {
                    int row = mw * 32 + mt * 16 + half * 8 + (lane >> 2);
                    float h0 = fast_tanh(acc[mt][nt][half * 2 + 0]);
                    float h1 = fast_tanh(acc[mt][nt][half * 2 + 1]);
                    *(__half2*)(smem + SM_STASH + row * STASH_STRIDE + col * 2) =
                        __floats2half2_rn(h0, h1);
                }
            }
    }
    __syncthreads();

    if (nw == 1) {
        // U warps: gate + weight + direct partial-score write (one warp per row band)
        float rowacc[4] = {0.f, 0.f, 0.f, 0.f};
#pragma unroll
        for (int mt = 0; mt < 2; mt++)
#pragma unroll
            for (int nt = 0; nt < 8; nt++) {
                int vcol = nt * 8 + (lane & 3) * 2;
                float w0 = ws[vcol + 0];
                float w1 = ws[vcol + 1];
#pragma unroll
                for (int half = 0; half < 2; half++) {
                    int row = mw * 32 + mt * 16 + half * 8 + (lane >> 2);
                    __half2 hh = *(const __half2*)(smem + SM_STASH +
                                                   row * STASH_STRIDE + vcol * 2);
                    float g0 = fast_sigmoid(acc[mt][nt][half * 2 + 0]);
                    float g1 = fast_sigmoid(acc[mt][nt][half * 2 + 1]);
                    rowacc[mt * 2 + half] += __low2float(hh)  * g0 * w0 +
                                             __high2float(hh) * g1 * w1;
                }
            }
#pragma unroll
        for (int ri = 0; ri < 4; ri++) {
            float p = rowacc[ri];
            p += __shfl_xor_sync(0xffffffffu, p, 1);
            p += __shfl_xor_sync(0xffffffffu, p, 2);
            if ((lane & 3) == 0) {
                int row = mw * 32 + (ri >> 1) * 16 + (ri & 1) * 8 + (lane >> 2);
                g_part[(size_t)task * BATCH + row] = p;
            }
        }
    }
}

// ---------------- softmax over instance axis (sums 8 l-chunk partials) ----------------
__global__ void softmax_kernel(float* __restrict__ out)
{
    const int b   = blockIdx.x;    // 0..127
    const int tid = threadIdx.x;   // 0..255 == n
    __shared__ float sh[256];

    const float* p = g_part + ((size_t)tid * 8) * BATCH + b;
    float s = 0.f;
#pragma unroll
    for (int j = 0; j < 8; j++) s += p[j * BATCH];
    sh[tid] = s;
    __syncthreads();
#pragma unroll
    for (int off = 128; off > 0; off >>= 1) {
        if (tid < off) sh[tid] = fmaxf(sh[tid], sh[tid + off]);
        __syncthreads();
    }
    float m = sh[0];
    __syncthreads();
    float e = __expf(s - m);
    sh[tid] = e;
    __syncthreads();
#pragma unroll
    for (int off = 128; off > 0; off >>= 1) {
        if (tid < off) sh[tid] += sh[tid + off];
        __syncthreads();
    }
    out[(size_t)tid * BATCH + b] = e / sh[0];
}

extern "C" void kernel_launch(void* const* d_in, const int* in_sizes, int n_in,
                              void* d_out, int out_size)
{
    const float* x = (const float*)d_in[0];
    const float* v = (const float*)d_in[1];
    const float* u = (const float*)d_in[2];
    const float* w = (const float*)d_in[3];
    float* out = (float*)d_out;

    cudaFuncSetAttribute(mil_gemm_kernel,
                         cudaFuncAttributeMaxDynamicSharedMemorySize, SM_TOTAL);

    prep_x_kernel<<<32768, 256>>>((const float4*)x);
    prep_vu_kernel<<<2048, 256>>>(v, u);
    mil_gemm_kernel<<<2048, 256, SM_TOTAL>>>(w);
    softmax_kernel<<<BATCH, 256>>>(out);
}